// round 16
// baseline (speedup 1.0000x reference)
#include <cuda_runtime.h>
#include <cstddef>
#include <cstdint>

#define BATCH 32
#define NUU   64
#define NYY   64
#define NXX   512
#define NWW   512
#define TSTEP 1024
#define RCTAS 128
#define RTHR  256
#define GROUPS 4
#define GCTAS 32
#define BGS   8
#define ROWS  16
#define PST   136

typedef unsigned long long u64;

#define FMA2(acc, w, h) asm("fma.rn.f32x2 %0, %1, %2, %0;" : "+l"(acc) : "l"(w), "l"(h))
__device__ __forceinline__ u64 dup2(float a) {
    u64 r;
    asm("mov.b64 %0, {%1, %1};" : "=l"(r) : "r"(__float_as_uint(a)));
    return r;
}

__device__ float d_Cv[NWW * NXX];
__device__ float d_Dv[NWW * NUU];
__device__ float d_bvv[NWW];
__device__ float d_X[NXX * NXX];
__device__ float d_X2[NXX * NXX];
__device__ float d_T1[NXX * NXX];
__device__ float d_Ahat[NXX * NXX];
__device__ float d_Bhat[NXX * NWW];
__device__ float d_B2hat[NXX * NUU];
__device__ float d_fbhat[NXX];
__device__ float d_utr[(size_t)TSTEP * BATCH * NUU];    // [t][b][k]
__device__ float d_states[(size_t)TSTEP * BATCH * NXX]; // [t][b][x]
__device__ float d_Wb[(size_t)TSTEP * BATCH * NWW];     // [t][b][j]
__device__ float d_hbuf[2 * GROUPS * NXX * BGS];
__device__ float d_wvec[GROUPS * NWW * BGS];
__device__ unsigned g_cw[GROUPS * 8 * 32];
__device__ unsigned g_ch[GROUPS * 8 * 32];
__device__ unsigned g_pcnt;

__device__ __forceinline__ void rel_add1(unsigned* cnt) {
    asm volatile("red.release.gpu.add.u32 [%0], 1;" :: "l"(cnt) : "memory");
}
__device__ __forceinline__ void wait_cnt(unsigned* cnt, unsigned target) {
    unsigned v;
    do {
        asm volatile("ld.acquire.gpu.u32 %0, [%1];" : "=r"(v) : "l"(cnt) : "memory");
    } while (v < target);
}
__device__ __forceinline__ float4 ldcg4(const float4* p) {
    float4 v;
    asm volatile("ld.global.cg.v4.f32 {%0,%1,%2,%3}, [%4];"
                 : "=f"(v.x), "=f"(v.y), "=f"(v.z), "=f"(v.w) : "l"(p));
    return v;
}

__global__ void prep_kernel(const float* __restrict__ C2, const float* __restrict__ mult,
                            const float* __restrict__ Dt, const float* __restrict__ E,
                            const float* __restrict__ bv) {
    int i = blockIdx.x * blockDim.x + threadIdx.x;
    int stride = gridDim.x * blockDim.x;
    if (i == 0) g_pcnt = 0u;
    for (int idx = i; idx < NWW; idx += stride) d_bvv[idx] = bv[idx];
    for (int idx = i; idx < NWW * NXX; idx += stride) {
        int r = idx / NXX;
        d_Cv[idx] = C2[idx] / mult[r];
    }
    for (int idx = i; idx < NWW * NUU; idx += stride) {
        int r = idx / NUU;
        d_Dv[idx] = Dt[idx] / mult[r];
    }
    for (int idx = i; idx < NXX * NXX; idx += stride) {
        int r = idx / NXX, c = idx % NXX;
        d_X[idx] = (r == c ? 2.0f : 0.0f) - E[idx];
    }
}

__global__ void utrans_kernel(const float* __restrict__ u) {
    __shared__ float tile[64][65];
    int tid = threadIdx.x;
    int t0 = blockIdx.x * 64, b = blockIdx.y;
    for (int i = tid; i < 64 * 64; i += 256) {
        int k = i >> 6, tt = i & 63;
        tile[tt][k] = u[(size_t)b * NUU * TSTEP + (size_t)k * TSTEP + t0 + tt];
    }
    __syncthreads();
    for (int i = tid; i < 64 * 64; i += 256) {
        int tt = i >> 6, k = i & 63;
        d_utr[((size_t)(t0 + tt) * BATCH + b) * NUU + k] = tile[tt][k];
    }
}

__device__ __forceinline__ void gemm_tile(const float* __restrict__ A, const float* __restrict__ Bm,
                                          float* __restrict__ C, int N, int K, int mode,
                                          int bx, int by,
                                          float (*As)[16][64], float (*Bs)[16][64]) {
    int tid = threadIdx.x;
    int tx = tid & 15, ty = tid >> 4;
    int ar = tid >> 2, ac = (tid & 3) << 2;
    int br = tid >> 4, bc = (tid & 15) << 2;
    const float* Aptr = A + (size_t)(by * 64 + ar) * K + ac;
    const float* Bptr = Bm + (size_t)br * N + bx * 64 + bc;

    float4 av = *(const float4*)Aptr;
    float4 bv = *(const float4*)Bptr;
    As[0][ac + 0][ar] = av.x; As[0][ac + 1][ar] = av.y;
    As[0][ac + 2][ar] = av.z; As[0][ac + 3][ar] = av.w;
    *(float4*)&Bs[0][br][bc] = bv;
    __syncthreads();

    float acc[4][4] = {};
    int buf = 0;
    for (int k0 = 16; k0 <= K; k0 += 16) {
        if (k0 < K) {
            av = *(const float4*)(Aptr + k0);
            bv = *(const float4*)(Bptr + (size_t)k0 * N);
        }
#pragma unroll
        for (int k = 0; k < 16; k++) {
            float4 a = *(const float4*)&As[buf][k][ty * 4];
            float4 b = *(const float4*)&Bs[buf][k][tx * 4];
            acc[0][0] = fmaf(a.x, b.x, acc[0][0]); acc[0][1] = fmaf(a.x, b.y, acc[0][1]);
            acc[0][2] = fmaf(a.x, b.z, acc[0][2]); acc[0][3] = fmaf(a.x, b.w, acc[0][3]);
            acc[1][0] = fmaf(a.y, b.x, acc[1][0]); acc[1][1] = fmaf(a.y, b.y, acc[1][1]);
            acc[1][2] = fmaf(a.y, b.z, acc[1][2]); acc[1][3] = fmaf(a.y, b.w, acc[1][3]);
            acc[2][0] = fmaf(a.z, b.x, acc[2][0]); acc[2][1] = fmaf(a.z, b.y, acc[2][1]);
            acc[2][2] = fmaf(a.z, b.z, acc[2][2]); acc[2][3] = fmaf(a.z, b.w, acc[2][3]);
            acc[3][0] = fmaf(a.w, b.x, acc[3][0]); acc[3][1] = fmaf(a.w, b.y, acc[3][1]);
            acc[3][2] = fmaf(a.w, b.z, acc[3][2]); acc[3][3] = fmaf(a.w, b.w, acc[3][3]);
        }
        if (k0 < K) {
            int nb = buf ^ 1;
            As[nb][ac + 0][ar] = av.x; As[nb][ac + 1][ar] = av.y;
            As[nb][ac + 2][ar] = av.z; As[nb][ac + 3][ar] = av.w;
            *(float4*)&Bs[nb][br][bc] = bv;
        }
        __syncthreads();
        buf ^= 1;
    }
#pragma unroll
    for (int i = 0; i < 4; i++) {
        int r = by * 64 + ty * 4 + i;
        float o[4];
#pragma unroll
        for (int j = 0; j < 4; j++) {
            int cx = bx * 64 + tx * 4 + j;
            float v = acc[i][j];
            if (mode) v = (r == cx ? 2.0f : 0.0f) - v;
            o[j] = v;
        }
        *(float4*)&C[(size_t)r * N + bx * 64 + tx * 4] = make_float4(o[0], o[1], o[2], o[3]);
    }
}

__device__ __forceinline__ void gbar(unsigned gen) {
    __threadfence();
    __syncthreads();
    if (threadIdx.x == 0) {
        rel_add1(&g_pcnt);
        wait_cnt(&g_pcnt, 64u * gen);
    }
    __syncthreads();
}

__global__ void __launch_bounds__(256, 1) prepgemm_kernel(
        const float* __restrict__ E, const float* __restrict__ F_w,
        const float* __restrict__ F_b, const float* __restrict__ B1_w,
        const float* __restrict__ B2_w) {
    __shared__ float As[2][16][64];
    __shared__ float Bs[2][16][64];
    int cta = blockIdx.x;
    int bx = cta & 7, by = cta >> 3;

    gemm_tile(E, d_X, d_T1, 512, 512, 1, bx, by, As, Bs);  gbar(1);
    gemm_tile(d_X, d_T1, d_X2, 512, 512, 0, bx, by, As, Bs); gbar(2);
    gemm_tile(E, d_X2, d_T1, 512, 512, 1, bx, by, As, Bs); gbar(3);
    gemm_tile(d_X2, d_T1, d_X, 512, 512, 0, bx, by, As, Bs); gbar(4);
    gemm_tile(E, d_X, d_T1, 512, 512, 1, bx, by, As, Bs);  gbar(5);
    gemm_tile(d_X, d_T1, d_X2, 512, 512, 0, bx, by, As, Bs); gbar(6);
    gemm_tile(d_X2, F_w, d_Ahat, 512, 512, 0, bx, by, As, Bs);
    gemm_tile(d_X2, B1_w, d_Bhat, 512, 512, 0, bx, by, As, Bs);
    if (cta < 8) {
        gemm_tile(d_X2, B2_w, d_B2hat, 64, 512, 0, 0, cta, As, Bs);
    } else if (cta < 16 && threadIdx.x < 64) {
        int r = (cta - 8) * 64 + threadIdx.x;
        float s = 0.f;
        for (int k = 0; k < NXX; k++) s = fmaf(d_X2[(size_t)r * NXX + k], F_b[k], s);
        d_fbhat[r] = s;
    }
}

__global__ void init_kernel() {
    int i = blockIdx.x * blockDim.x + threadIdx.x;
    int stride = gridDim.x * blockDim.x;
    for (int idx = i; idx < GROUPS * 8 * 32; idx += stride) {
        g_cw[idx] = 0u;
        g_ch[idx] = 0u;
    }
    for (int idx = i; idx < 2 * GROUPS * NXX * BGS; idx += stride) d_hbuf[idx] = 0.f;
    for (int idx = i; idx < BATCH * NXX; idx += stride) d_states[idx] = 0.f;
}

__device__ __forceinline__ void dotp2(const float* __restrict__ hp,
                                      const float* __restrict__ wkb,
                                      int kbase, u64* __restrict__ acc) {
#pragma unroll
    for (int i = 0; i < 16; i++) {
        int k = kbase + 4 * i;
        u64 h2 = dup2(hp[k * BGS]);
        const ulonglong2* wp = (const ulonglong2*)(wkb + k * ROWS);
        ulonglong2 w01 = wp[0], w23 = wp[1], w45 = wp[2], w67 = wp[3];
        FMA2(acc[0], w01.x, h2); FMA2(acc[1], w01.y, h2);
        FMA2(acc[2], w23.x, h2); FMA2(acc[3], w23.y, h2);
        FMA2(acc[4], w45.x, h2); FMA2(acc[5], w45.y, h2);
        FMA2(acc[6], w67.x, h2); FMA2(acc[7], w67.y, h2);
    }
}

__global__ void __launch_bounds__(RTHR, 1) recur_kernel() {
    extern __shared__ float sm[];
    float* wC  = sm;
    float* wA  = wC + 8192;
    float* wB  = wA + 8192;
    float* h_s = wB + 8192;
    float* w_s = h_s + NXX * BGS;
    float* pW  = w_s + NWW * BGS;
    float* pA  = pW + 32 * PST;
    float* pB  = pA + 32 * PST;
    float* uDv = pB + 32 * PST;       // [16][64]
    float* uB2 = uDv + 1024;          // [16][64]
    float* fbh = uB2 + 1024;          // [16] fbhat slice
    float* bvh = fbh + 16;            // [16] bv slice
    float* u_sl = bvh + 16;           // [2][512]

    int tid  = threadIdx.x;
    int cta  = blockIdx.x;
    int g    = cta >> 5;
    int lc   = cta & 31;
    int j0   = lc * ROWS;
    int warp = tid >> 5, lane = tid & 31;
    int kh = lane >> 3, b = lane & 7;
    int rrow = tid & 15, rb = tid >> 4;
    int bb = g * BGS + rb;

    unsigned* cw_arr = &g_cw[(g * 8 + (lc >> 2)) * 32];
    unsigned* ch_arr = &g_ch[(g * 8 + (lc >> 2)) * 32];
    unsigned* cw_poll = &g_cw[(g * 8 + warp) * 32];
    unsigned* ch_poll = &g_ch[(g * 8 + warp) * 32];

    float* wg = d_wvec + g * NWW * BGS;

    for (int i = tid; i < 8192; i += RTHR) {
        int k = i >> 4, c = i & 15;
        wC[i] = d_Cv[(size_t)(j0 + c) * NXX + k];
        wA[i] = d_Ahat[(size_t)(j0 + c) * NXX + k];
        wB[i] = d_Bhat[(size_t)(j0 + c) * NWW + k];
    }
    for (int i = tid; i < 1024; i += RTHR) {
        int r = i >> 6, k = i & 63;
        uDv[i] = d_Dv[(size_t)(j0 + r) * NUU + k];
        uB2[i] = d_B2hat[(size_t)(j0 + r) * NUU + k];
    }
    if (tid < 16) {
        fbh[tid] = d_fbhat[j0 + tid];
        bvh[tid] = d_bvv[j0 + tid];
    }
    {
        const float* src = d_utr + (size_t)g * BGS * NUU;
        for (int i = tid; i < 512; i += RTHR) u_sl[i] = src[i];
    }
    __syncthreads();

    int kbase = warp * 64 + kh;
    int slot = warp * 4 + kh;
    u64* ppW = (u64*)(pW + slot * PST + b * 16);
    u64* ppA = (u64*)(pA + slot * PST + b * 16);
    u64* ppB = (u64*)(pB + slot * PST + b * 16);
    int roff = rb * 16 + rrow;

    for (int t = 0; t < TSTEP; t++) {
        float g1 = 0.f, g2 = 0.f;
        if (tid < 128) {
            const float* uu = u_sl + (t & 1) * 512 + rb * 64;
            const float* dv = uDv + rrow * 64;
            const float* b2 = uB2 + rrow * 64;
            float s1 = 0.f, s2 = 0.f;
#pragma unroll 16
            for (int k = 0; k < 64; k++) {
                float uv = uu[k];
                s1 = fmaf(dv[k], uv, s1);
                s2 = fmaf(b2[k], uv, s2);
            }
            g1 = s1 + bvh[rrow];
            g2 = s2 + fbh[rrow];
        }
        if (t > 0) {
            if (lane == 0) wait_cnt(ch_poll, 512u * (unsigned)t);
            __syncwarp();
        }
        {
            const float4* src = (const float4*)(d_hbuf +
                ((size_t)(t & 1) * GROUPS + g) * (NXX * BGS)) + warp * 128;
            float4* dst = (float4*)h_s + warp * 128;
#pragma unroll
            for (int i = 0; i < 4; i++) dst[lane + 32 * i] = ldcg4(&src[lane + 32 * i]);
        }
        __syncwarp();
        {
            u64 acc[8] = {};
            dotp2(h_s + b, wC, kbase, acc);
#pragma unroll
            for (int r = 0; r < 8; r++) ppW[r] = acc[r];
        }
        __syncthreads();  // S1
        if (tid < 128) {
            float v = g1;
#pragma unroll
            for (int p = 0; p < 32; p++) v += pW[p * PST + roff];
            v = fmaxf(v, 0.f);
            wg[(j0 + rrow) * BGS + rb] = v;
            rel_add1(cw_arr);
            d_Wb[((size_t)t * BATCH + bb) * NWW + j0 + rrow] = v;
        } else if (t < TSTEP - 1) {
            const float* src = d_utr + ((size_t)(t + 1) * BATCH + g * BGS) * NUU;
            float* dst = u_sl + ((t + 1) & 1) * 512;
            int i = (tid - 128) * 4;
            *(float4*)&dst[i] = ldcg4((const float4*)&src[i]);
        }
        if (t == TSTEP - 1) break;
        {
            u64 acc[8] = {};
            dotp2(h_s + b, wA, kbase, acc);
#pragma unroll
            for (int r = 0; r < 8; r++) ppA[r] = acc[r];
        }
        if (lane == 0) wait_cnt(cw_poll, 512u * (unsigned)(t + 1));
        __syncwarp();
        {
            const float4* src = (const float4*)wg + warp * 128;
            float4* dst = (float4*)w_s + warp * 128;
#pragma unroll
            for (int i = 0; i < 4; i++) dst[lane + 32 * i] = ldcg4(&src[lane + 32 * i]);
        }
        __syncwarp();
        {
            u64 acc[8] = {};
            dotp2(w_s + b, wB, kbase, acc);
#pragma unroll
            for (int r = 0; r < 8; r++) ppB[r] = acc[r];
        }
        __syncthreads();  // S3 (also publishes u slab for t+1)
        if (tid < 128) {
            float v = g2;
#pragma unroll
            for (int p = 0; p < 32; p++)
                v += pA[p * PST + roff] + pB[p * PST + roff];
            d_hbuf[((size_t)((t + 1) & 1) * GROUPS + g) * (NXX * BGS) + (j0 + rrow) * BGS + rb] = v;
            rel_add1(ch_arr);
            d_states[((size_t)(t + 1) * BATCH + bb) * NXX + j0 + rrow] = v;
        }
    }
}

__global__ void yfinal_kernel(const float* __restrict__ u, const float* __restrict__ C1,
                              const float* __restrict__ D11, const float* __restrict__ D12,
                              const float* __restrict__ by, float* __restrict__ out) {
    __shared__ float As[64][65];
    __shared__ float Bs[64][68];
    int tid = threadIdx.x;
    int tx = tid & 15, ty = tid >> 4;
    int t0 = blockIdx.x * 64, b = blockIdx.y;
    float acc[4][4] = {};
    for (int seg = 0; seg < 3; seg++) {
        int nchunk = (seg == 2) ? 1 : 8;
        const float* Am = (seg == 0) ? C1 : (seg == 1) ? D11 : D12;
        int Ksz = (seg == 2) ? 64 : 512;
        for (int ch = 0; ch < nchunk; ch++) {
            int x0 = ch * 64;
            for (int i = tid; i < 64 * 64; i += 256) {
                int j = i >> 6, k = i & 63;
                As[j][k] = Am[(size_t)j * Ksz + x0 + k];
            }
            if (seg == 2) {
                for (int i = tid; i < 64 * 64; i += 256) {
                    int k = i >> 6, tt = i & 63;
                    Bs[k][tt] = u[((size_t)b * NUU + k) * TSTEP + t0 + tt];
                }
            } else {
                const float* S = (seg == 0) ? d_states : d_Wb;
                for (int i = tid; i < 64 * 64; i += 256) {
                    int tt = i >> 6, xx = i & 63;
                    Bs[xx][tt] = S[((size_t)(t0 + tt) * BATCH + b) * 512 + x0 + xx];
                }
            }
            __syncthreads();
#pragma unroll 8
            for (int k = 0; k < 64; k++) {
                float a0 = As[ty * 4 + 0][k];
                float a1 = As[ty * 4 + 1][k];
                float a2 = As[ty * 4 + 2][k];
                float a3 = As[ty * 4 + 3][k];
                float4 bv = *(const float4*)&Bs[k][tx * 4];
                acc[0][0] = fmaf(a0, bv.x, acc[0][0]); acc[0][1] = fmaf(a0, bv.y, acc[0][1]);
                acc[0][2] = fmaf(a0, bv.z, acc[0][2]); acc[0][3] = fmaf(a0, bv.w, acc[0][3]);
                acc[1][0] = fmaf(a1, bv.x, acc[1][0]); acc[1][1] = fmaf(a1, bv.y, acc[1][1]);
                acc[1][2] = fmaf(a1, bv.z, acc[1][2]); acc[1][3] = fmaf(a1, bv.w, acc[1][3]);
                acc[2][0] = fmaf(a2, bv.x, acc[2][0]); acc[2][1] = fmaf(a2, bv.y, acc[2][1]);
                acc[2][2] = fmaf(a2, bv.z, acc[2][2]); acc[2][3] = fmaf(a2, bv.w, acc[2][3]);
                acc[3][0] = fmaf(a3, bv.x, acc[3][0]); acc[3][1] = fmaf(a3, bv.y, acc[3][1]);
                acc[3][2] = fmaf(a3, bv.z, acc[3][2]); acc[3][3] = fmaf(a3, bv.w, acc[3][3]);
            }
            __syncthreads();
        }
    }
#pragma unroll
    for (int i = 0; i < 4; i++) {
        int j = ty * 4 + i;
        float bj = by[j];
        float4 o = make_float4(acc[i][0] + bj, acc[i][1] + bj, acc[i][2] + bj, acc[i][3] + bj);
        *(float4*)&out[((size_t)b * NYY + j) * TSTEP + t0 + tx * 4] = o;
    }
}

extern "C" void kernel_launch(void* const* d_in, const int* in_sizes, int n_in,
                              void* d_out, int out_size) {
    const float* u      = (const float*)d_in[0];
    const float* E      = (const float*)d_in[1];
    const float* F_w    = (const float*)d_in[2];
    const float* F_b    = (const float*)d_in[3];
    const float* B1_w   = (const float*)d_in[4];
    const float* B2_w   = (const float*)d_in[5];
    const float* C2tild = (const float*)d_in[6];
    const float* bv     = (const float*)d_in[7];
    const float* Dtild  = (const float*)d_in[8];
    const float* C1_w   = (const float*)d_in[9];
    const float* D11_w  = (const float*)d_in[10];
    const float* D12_w  = (const float*)d_in[11];
    const float* by     = (const float*)d_in[12];
    const float* multis = (const float*)d_in[13];
    float* out = (float*)d_out;

    const int SMEM_RECUR =
        (3 * 8192 + 2 * 4096 + 3 * 32 * PST + 2 * 1024 + 32 + 2 * 512) * 4;
    cudaFuncSetAttribute(recur_kernel, cudaFuncAttributeMaxDynamicSharedMemorySize, SMEM_RECUR);

    prep_kernel<<<256, 256>>>(C2tild, multis, Dtild, E, bv);
    utrans_kernel<<<dim3(16, 32), 256>>>(u);
    prepgemm_kernel<<<64, 256>>>(E, F_w, F_b, B1_w, B2_w);
    init_kernel<<<64, 256>>>();
    recur_kernel<<<RCTAS, RTHR, SMEM_RECUR>>>();
    yfinal_kernel<<<dim3(16, 32), 256>>>(u, C1_w, D11_w, D12_w, by, out);
}

// round 17
// speedup vs baseline: 2.2702x; 2.2702x over previous
#include <cuda_runtime.h>
#include <cstddef>
#include <cstdint>

#define BATCH 32
#define NUU   64
#define NYY   64
#define NXX   512
#define NWW   512
#define TSTEP 1024
#define RCTAS 128
#define RTHR  256
#define GROUPS 4
#define GCTAS 32
#define BGS   8
#define ROWS  16
#define PST   136

typedef unsigned long long u64;

#define FMA2(acc, w, h) asm("fma.rn.f32x2 %0, %1, %2, %0;" : "+l"(acc) : "l"(w), "l"(h))
__device__ __forceinline__ u64 dup2(float a) {
    u64 r;
    asm("mov.b64 %0, {%1, %1};" : "=l"(r) : "r"(__float_as_uint(a)));
    return r;
}

__device__ float d_Cv[NWW * NXX];
__device__ float d_Dv[NWW * NUU];
__device__ float d_bvv[NWW];
__device__ float d_X[NXX * NXX];
__device__ float d_X2[NXX * NXX];
__device__ float d_T1[NXX * NXX];
__device__ float d_Ahat[NXX * NXX];
__device__ float d_Bhat[NXX * NWW];
__device__ float d_B2hat[NXX * NUU];
__device__ float d_fbhat[NXX];
__device__ float d_utr[(size_t)TSTEP * BATCH * NUU];    // [t][b][k]
__device__ float d_states[(size_t)TSTEP * BATCH * NXX]; // [t][b][x]
__device__ float d_Wb[(size_t)TSTEP * BATCH * NWW];     // [t][b][j]
__device__ float d_hbuf[2 * GROUPS * NXX * BGS];
__device__ float d_wvec[GROUPS * NWW * BGS];
__device__ unsigned g_cw[GROUPS * 8 * 32];
__device__ unsigned g_ch[GROUPS * 8 * 32];
__device__ unsigned g_pcnt;

__device__ __forceinline__ void rel_add1(unsigned* cnt) {
    asm volatile("red.release.gpu.add.u32 [%0], 1;" :: "l"(cnt) : "memory");
}
__device__ __forceinline__ void wait_cnt(unsigned* cnt, unsigned target) {
    unsigned v;
    do {
        asm volatile("ld.acquire.gpu.u32 %0, [%1];" : "=r"(v) : "l"(cnt) : "memory");
    } while (v < target);
}
__device__ __forceinline__ float4 ldcg4(const float4* p) {
    float4 v;
    asm volatile("ld.global.cg.v4.f32 {%0,%1,%2,%3}, [%4];"
                 : "=f"(v.x), "=f"(v.y), "=f"(v.z), "=f"(v.w) : "l"(p));
    return v;
}

__global__ void prep_kernel(const float* __restrict__ C2, const float* __restrict__ mult,
                            const float* __restrict__ Dt, const float* __restrict__ E,
                            const float* __restrict__ bv) {
    int i = blockIdx.x * blockDim.x + threadIdx.x;
    int stride = gridDim.x * blockDim.x;
    if (i == 0) g_pcnt = 0u;
    for (int idx = i; idx < NWW; idx += stride) d_bvv[idx] = bv[idx];
    for (int idx = i; idx < NWW * NXX; idx += stride) {
        int r = idx / NXX;
        d_Cv[idx] = C2[idx] / mult[r];
    }
    for (int idx = i; idx < NWW * NUU; idx += stride) {
        int r = idx / NUU;
        d_Dv[idx] = Dt[idx] / mult[r];
    }
    for (int idx = i; idx < NXX * NXX; idx += stride) {
        int r = idx / NXX, c = idx % NXX;
        d_X[idx] = (r == c ? 2.0f : 0.0f) - E[idx];
    }
}

__global__ void utrans_kernel(const float* __restrict__ u) {
    __shared__ float tile[64][65];
    int tid = threadIdx.x;
    int t0 = blockIdx.x * 64, b = blockIdx.y;
    for (int i = tid; i < 64 * 64; i += 256) {
        int k = i >> 6, tt = i & 63;
        tile[tt][k] = u[(size_t)b * NUU * TSTEP + (size_t)k * TSTEP + t0 + tt];
    }
    __syncthreads();
    for (int i = tid; i < 64 * 64; i += 256) {
        int tt = i >> 6, k = i & 63;
        d_utr[((size_t)(t0 + tt) * BATCH + b) * NUU + k] = tile[tt][k];
    }
}

__device__ __forceinline__ void gemm_tile(const float* __restrict__ A, const float* __restrict__ Bm,
                                          float* __restrict__ C, int N, int K, int mode,
                                          int bx, int by,
                                          float (*As)[16][64], float (*Bs)[16][64]) {
    int tid = threadIdx.x;
    int tx = tid & 15, ty = tid >> 4;
    int ar = tid >> 2, ac = (tid & 3) << 2;
    int br = tid >> 4, bc = (tid & 15) << 2;
    const float* Aptr = A + (size_t)(by * 64 + ar) * K + ac;
    const float* Bptr = Bm + (size_t)br * N + bx * 64 + bc;

    float4 av = *(const float4*)Aptr;
    float4 bv = *(const float4*)Bptr;
    As[0][ac + 0][ar] = av.x; As[0][ac + 1][ar] = av.y;
    As[0][ac + 2][ar] = av.z; As[0][ac + 3][ar] = av.w;
    *(float4*)&Bs[0][br][bc] = bv;
    __syncthreads();

    float acc[4][4] = {};
    int buf = 0;
    for (int k0 = 16; k0 <= K; k0 += 16) {
        if (k0 < K) {
            av = *(const float4*)(Aptr + k0);
            bv = *(const float4*)(Bptr + (size_t)k0 * N);
        }
#pragma unroll
        for (int k = 0; k < 16; k++) {
            float4 a = *(const float4*)&As[buf][k][ty * 4];
            float4 b = *(const float4*)&Bs[buf][k][tx * 4];
            acc[0][0] = fmaf(a.x, b.x, acc[0][0]); acc[0][1] = fmaf(a.x, b.y, acc[0][1]);
            acc[0][2] = fmaf(a.x, b.z, acc[0][2]); acc[0][3] = fmaf(a.x, b.w, acc[0][3]);
            acc[1][0] = fmaf(a.y, b.x, acc[1][0]); acc[1][1] = fmaf(a.y, b.y, acc[1][1]);
            acc[1][2] = fmaf(a.y, b.z, acc[1][2]); acc[1][3] = fmaf(a.y, b.w, acc[1][3]);
            acc[2][0] = fmaf(a.z, b.x, acc[2][0]); acc[2][1] = fmaf(a.z, b.y, acc[2][1]);
            acc[2][2] = fmaf(a.z, b.z, acc[2][2]); acc[2][3] = fmaf(a.z, b.w, acc[2][3]);
            acc[3][0] = fmaf(a.w, b.x, acc[3][0]); acc[3][1] = fmaf(a.w, b.y, acc[3][1]);
            acc[3][2] = fmaf(a.w, b.z, acc[3][2]); acc[3][3] = fmaf(a.w, b.w, acc[3][3]);
        }
        if (k0 < K) {
            int nb = buf ^ 1;
            As[nb][ac + 0][ar] = av.x; As[nb][ac + 1][ar] = av.y;
            As[nb][ac + 2][ar] = av.z; As[nb][ac + 3][ar] = av.w;
            *(float4*)&Bs[nb][br][bc] = bv;
        }
        __syncthreads();
        buf ^= 1;
    }
#pragma unroll
    for (int i = 0; i < 4; i++) {
        int r = by * 64 + ty * 4 + i;
        float o[4];
#pragma unroll
        for (int j = 0; j < 4; j++) {
            int cx = bx * 64 + tx * 4 + j;
            float v = acc[i][j];
            if (mode) v = (r == cx ? 2.0f : 0.0f) - v;
            o[j] = v;
        }
        *(float4*)&C[(size_t)r * N + bx * 64 + tx * 4] = make_float4(o[0], o[1], o[2], o[3]);
    }
}

__device__ __forceinline__ void gbar(unsigned gen) {
    __threadfence();
    __syncthreads();
    if (threadIdx.x == 0) {
        rel_add1(&g_pcnt);
        wait_cnt(&g_pcnt, 64u * gen);
    }
    __syncthreads();
}

__global__ void __launch_bounds__(256, 1) prepgemm_kernel(
        const float* __restrict__ E, const float* __restrict__ F_w,
        const float* __restrict__ F_b, const float* __restrict__ B1_w,
        const float* __restrict__ B2_w) {
    __shared__ float As[2][16][64];
    __shared__ float Bs[2][16][64];
    int cta = blockIdx.x;
    int bx = cta & 7, by = cta >> 3;

    gemm_tile(E, d_X, d_T1, 512, 512, 1, bx, by, As, Bs);  gbar(1);
    gemm_tile(d_X, d_T1, d_X2, 512, 512, 0, bx, by, As, Bs); gbar(2);
    gemm_tile(E, d_X2, d_T1, 512, 512, 1, bx, by, As, Bs); gbar(3);
    gemm_tile(d_X2, d_T1, d_X, 512, 512, 0, bx, by, As, Bs); gbar(4);
    gemm_tile(E, d_X, d_T1, 512, 512, 1, bx, by, As, Bs);  gbar(5);
    gemm_tile(d_X, d_T1, d_X2, 512, 512, 0, bx, by, As, Bs); gbar(6);
    gemm_tile(d_X2, F_w, d_Ahat, 512, 512, 0, bx, by, As, Bs);
    gemm_tile(d_X2, B1_w, d_Bhat, 512, 512, 0, bx, by, As, Bs);
    if (cta < 8) {
        gemm_tile(d_X2, B2_w, d_B2hat, 64, 512, 0, 0, cta, As, Bs);
    } else if (cta < 16 && threadIdx.x < 64) {
        int r = (cta - 8) * 64 + threadIdx.x;
        float s = 0.f;
        for (int k = 0; k < NXX; k++) s = fmaf(d_X2[(size_t)r * NXX + k], F_b[k], s);
        d_fbhat[r] = s;
    }
}

__global__ void init_kernel() {
    int i = blockIdx.x * blockDim.x + threadIdx.x;
    int stride = gridDim.x * blockDim.x;
    for (int idx = i; idx < GROUPS * 8 * 32; idx += stride) {
        g_cw[idx] = 0u;
        g_ch[idx] = 0u;
    }
    for (int idx = i; idx < 2 * GROUPS * NXX * BGS; idx += stride) d_hbuf[idx] = 0.f;
    for (int idx = i; idx < BATCH * NXX; idx += stride) d_states[idx] = 0.f;
}

__device__ __forceinline__ void dotp2(const float* __restrict__ hp,
                                      const float* __restrict__ wkb,
                                      int kbase, u64* __restrict__ acc) {
#pragma unroll
    for (int i = 0; i < 16; i++) {
        int k = kbase + 4 * i;
        u64 h2 = dup2(hp[k * BGS]);
        const ulonglong2* wp = (const ulonglong2*)(wkb + k * ROWS);
        ulonglong2 w01 = wp[0], w23 = wp[1], w45 = wp[2], w67 = wp[3];
        FMA2(acc[0], w01.x, h2); FMA2(acc[1], w01.y, h2);
        FMA2(acc[2], w23.x, h2); FMA2(acc[3], w23.y, h2);
        FMA2(acc[4], w45.x, h2); FMA2(acc[5], w45.y, h2);
        FMA2(acc[6], w67.x, h2); FMA2(acc[7], w67.y, h2);
    }
}

__global__ void __launch_bounds__(RTHR, 1) recur_kernel() {
    extern __shared__ float sm[];
    float* wC  = sm;
    float* wA  = wC + 8192;
    float* wB  = wA + 8192;
    float* h_s = wB + 8192;
    float* w_s = h_s + NXX * BGS;
    float* pW  = w_s + NWW * BGS;
    float* pA  = pW + 32 * PST;
    float* pB  = pA + 32 * PST;
    float* uDv = pB + 32 * PST;       // [k(64)][16]  (transposed: conflict-free)
    float* uB2 = uDv + 1024;          // [k(64)][16]
    float* fbh = uB2 + 1024;          // [16]
    float* bvh = fbh + 16;            // [16]
    float* u_sl = bvh + 16;           // [2][512]

    int tid  = threadIdx.x;
    int cta  = blockIdx.x;
    int g    = cta >> 5;
    int lc   = cta & 31;
    int j0   = lc * ROWS;
    int warp = tid >> 5, lane = tid & 31;
    int kh = lane >> 3, b = lane & 7;
    int rrow = tid & 15, rb = tid >> 4;
    int bb = g * BGS + rb;

    unsigned* cw_arr = &g_cw[(g * 8 + (lc >> 2)) * 32];
    unsigned* ch_arr = &g_ch[(g * 8 + (lc >> 2)) * 32];
    unsigned* cw_poll = &g_cw[(g * 8 + warp) * 32];
    unsigned* ch_poll = &g_ch[(g * 8 + warp) * 32];

    float* wg = d_wvec + g * NWW * BGS;

    for (int i = tid; i < 8192; i += RTHR) {
        int k = i >> 4, c = i & 15;
        wC[i] = d_Cv[(size_t)(j0 + c) * NXX + k];
        wA[i] = d_Ahat[(size_t)(j0 + c) * NXX + k];
        wB[i] = d_Bhat[(size_t)(j0 + c) * NWW + k];
    }
    // stage Dv / B2hat slices TRANSPOSED [k][16]
    for (int i = tid; i < 1024; i += RTHR) {
        int r = i & 15, k = i >> 4;
        uDv[k * 16 + r] = d_Dv[(size_t)(j0 + r) * NUU + k];
        uB2[k * 16 + r] = d_B2hat[(size_t)(j0 + r) * NUU + k];
    }
    if (tid < 16) {
        fbh[tid] = d_fbhat[j0 + tid];
        bvh[tid] = d_bvv[j0 + tid];
    }
    {
        const float* src = d_utr + (size_t)g * BGS * NUU;
        for (int i = tid; i < 512; i += RTHR) u_sl[i] = src[i];
    }
    __syncthreads();

    int kbase = warp * 64 + kh;
    int slot = warp * 4 + kh;
    u64* ppW = (u64*)(pW + slot * PST + b * 16);
    u64* ppA = (u64*)(pA + slot * PST + b * 16);
    u64* ppB = (u64*)(pB + slot * PST + b * 16);
    int roff = rb * 16 + rrow;

    for (int t = 0; t < TSTEP; t++) {
        // on-the-fly G terms (conflict-free [k][16] layout); hides under h-poll
        float g1 = 0.f, g2 = 0.f;
        if (tid < 128) {
            const float* uu = u_sl + (t & 1) * 512 + rb * 64;
            float s1 = 0.f, s2 = 0.f;
#pragma unroll 16
            for (int k = 0; k < 64; k++) {
                float uv = uu[k];
                s1 = fmaf(uDv[k * 16 + rrow], uv, s1);
                s2 = fmaf(uB2[k * 16 + rrow], uv, s2);
            }
            g1 = s1 + bvh[rrow];
            g2 = s2 + fbh[rrow];
        }
        if (t > 0) {
            if (lane == 0) wait_cnt(ch_poll, 512u * (unsigned)t);
            __syncwarp();
        }
        {
            const float4* src = (const float4*)(d_hbuf +
                ((size_t)(t & 1) * GROUPS + g) * (NXX * BGS)) + warp * 128;
            float4* dst = (float4*)h_s + warp * 128;
#pragma unroll
            for (int i = 0; i < 4; i++) dst[lane + 32 * i] = ldcg4(&src[lane + 32 * i]);
        }
        __syncwarp();
        {
            u64 acc[8] = {};
            dotp2(h_s + b, wC, kbase, acc);
#pragma unroll
            for (int r = 0; r < 8; r++) ppW[r] = acc[r];
        }
        __syncthreads();  // S1
        if (tid < 128) {
            float v = g1;
#pragma unroll
            for (int p = 0; p < 32; p++) v += pW[p * PST + roff];
            v = fmaxf(v, 0.f);
            wg[(j0 + rrow) * BGS + rb] = v;
            rel_add1(cw_arr);
            d_Wb[((size_t)t * BATCH + bb) * NWW + j0 + rrow] = v;
        } else if (t < TSTEP - 1) {
            const float* src = d_utr + ((size_t)(t + 1) * BATCH + g * BGS) * NUU;
            float* dst = u_sl + ((t + 1) & 1) * 512;
            int i = (tid - 128) * 4;
            *(float4*)&dst[i] = ldcg4((const float4*)&src[i]);
        }
        if (t == TSTEP - 1) break;
        {
            u64 acc[8] = {};
            dotp2(h_s + b, wA, kbase, acc);
#pragma unroll
            for (int r = 0; r < 8; r++) ppA[r] = acc[r];
        }
        if (lane == 0) wait_cnt(cw_poll, 512u * (unsigned)(t + 1));
        __syncwarp();
        {
            const float4* src = (const float4*)wg + warp * 128;
            float4* dst = (float4*)w_s + warp * 128;
#pragma unroll
            for (int i = 0; i < 4; i++) dst[lane + 32 * i] = ldcg4(&src[lane + 32 * i]);
        }
        __syncwarp();
        {
            u64 acc[8] = {};
            dotp2(w_s + b, wB, kbase, acc);
#pragma unroll
            for (int r = 0; r < 8; r++) ppB[r] = acc[r];
        }
        __syncthreads();  // S3 (also publishes u slab for t+1)
        if (tid < 128) {
            float v = g2;
#pragma unroll
            for (int p = 0; p < 32; p++)
                v += pA[p * PST + roff] + pB[p * PST + roff];
            d_hbuf[((size_t)((t + 1) & 1) * GROUPS + g) * (NXX * BGS) + (j0 + rrow) * BGS + rb] = v;
            rel_add1(ch_arr);
            d_states[((size_t)(t + 1) * BATCH + bb) * NXX + j0 + rrow] = v;
        }
    }
}

__global__ void yfinal_kernel(const float* __restrict__ u, const float* __restrict__ C1,
                              const float* __restrict__ D11, const float* __restrict__ D12,
                              const float* __restrict__ by, float* __restrict__ out) {
    __shared__ float As[64][65];
    __shared__ float Bs[64][68];
    int tid = threadIdx.x;
    int tx = tid & 15, ty = tid >> 4;
    int t0 = blockIdx.x * 64, b = blockIdx.y;
    float acc[4][4] = {};
    for (int seg = 0; seg < 3; seg++) {
        int nchunk = (seg == 2) ? 1 : 8;
        const float* Am = (seg == 0) ? C1 : (seg == 1) ? D11 : D12;
        int Ksz = (seg == 2) ? 64 : 512;
        for (int ch = 0; ch < nchunk; ch++) {
            int x0 = ch * 64;
            for (int i = tid; i < 64 * 64; i += 256) {
                int j = i >> 6, k = i & 63;
                As[j][k] = Am[(size_t)j * Ksz + x0 + k];
            }
            if (seg == 2) {
                for (int i = tid; i < 64 * 64; i += 256) {
                    int k = i >> 6, tt = i & 63;
                    Bs[k][tt] = u[((size_t)b * NUU + k) * TSTEP + t0 + tt];
                }
            } else {
                const float* S = (seg == 0) ? d_states : d_Wb;
                for (int i = tid; i < 64 * 64; i += 256) {
                    int tt = i >> 6, xx = i & 63;
                    Bs[xx][tt] = S[((size_t)(t0 + tt) * BATCH + b) * 512 + x0 + xx];
                }
            }
            __syncthreads();
#pragma unroll 8
            for (int k = 0; k < 64; k++) {
                float a0 = As[ty * 4 + 0][k];
                float a1 = As[ty * 4 + 1][k];
                float a2 = As[ty * 4 + 2][k];
                float a3 = As[ty * 4 + 3][k];
                float4 bv = *(const float4*)&Bs[k][tx * 4];
                acc[0][0] = fmaf(a0, bv.x, acc[0][0]); acc[0][1] = fmaf(a0, bv.y, acc[0][1]);
                acc[0][2] = fmaf(a0, bv.z, acc[0][2]); acc[0][3] = fmaf(a0, bv.w, acc[0][3]);
                acc[1][0] = fmaf(a1, bv.x, acc[1][0]); acc[1][1] = fmaf(a1, bv.y, acc[1][1]);
                acc[1][2] = fmaf(a1, bv.z, acc[1][2]); acc[1][3] = fmaf(a1, bv.w, acc[1][3]);
                acc[2][0] = fmaf(a2, bv.x, acc[2][0]); acc[2][1] = fmaf(a2, bv.y, acc[2][1]);
                acc[2][2] = fmaf(a2, bv.z, acc[2][2]); acc[2][3] = fmaf(a2, bv.w, acc[2][3]);
                acc[3][0] = fmaf(a3, bv.x, acc[3][0]); acc[3][1] = fmaf(a3, bv.y, acc[3][1]);
                acc[3][2] = fmaf(a3, bv.z, acc[3][2]); acc[3][3] = fmaf(a3, bv.w, acc[3][3]);
            }
            __syncthreads();
        }
    }
#pragma unroll
    for (int i = 0; i < 4; i++) {
        int j = ty * 4 + i;
        float bj = by[j];
        float4 o = make_float4(acc[i][0] + bj, acc[i][1] + bj, acc[i][2] + bj, acc[i][3] + bj);
        *(float4*)&out[((size_t)b * NYY + j) * TSTEP + t0 + tx * 4] = o;
    }
}

extern "C" void kernel_launch(void* const* d_in, const int* in_sizes, int n_in,
                              void* d_out, int out_size) {
    const float* u      = (const float*)d_in[0];
    const float* E      = (const float*)d_in[1];
    const float* F_w    = (const float*)d_in[2];
    const float* F_b    = (const float*)d_in[3];
    const float* B1_w   = (const float*)d_in[4];
    const float* B2_w   = (const float*)d_in[5];
    const float* C2tild = (const float*)d_in[6];
    const float* bv     = (const float*)d_in[7];
    const float* Dtild  = (const float*)d_in[8];
    const float* C1_w   = (const float*)d_in[9];
    const float* D11_w  = (const float*)d_in[10];
    const float* D12_w  = (const float*)d_in[11];
    const float* by     = (const float*)d_in[12];
    const float* multis = (const float*)d_in[13];
    float* out = (float*)d_out;

    const int SMEM_RECUR =
        (3 * 8192 + 2 * 4096 + 3 * 32 * PST + 2 * 1024 + 32 + 2 * 512) * 4;
    cudaFuncSetAttribute(recur_kernel, cudaFuncAttributeMaxDynamicSharedMemorySize, SMEM_RECUR);

    prep_kernel<<<256, 256>>>(C2tild, multis, Dtild, E, bv);
    utrans_kernel<<<dim3(16, 32), 256>>>(u);
    prepgemm_kernel<<<64, 256>>>(E, F_w, F_b, B1_w, B2_w);
    init_kernel<<<64, 256>>>();
    recur_kernel<<<RCTAS, RTHR, SMEM_RECUR>>>();
    yfinal_kernel<<<dim3(16, 32), 256>>>(u, C1_w, D11_w, D12_w, by, out);
}